// round 14
// baseline (speedup 1.0000x reference)
#include <cuda_runtime.h>
#include <cuda_fp16.h>
#include <math.h>
#include <stdint.h>

// ===========================================================================
// Problem constants
// ===========================================================================
#define B_ROWS 8192
#define P_ROWS 4096
#define D_DIM  512
#define NCHUNK (P_ROWS / 128)     // 32 column chunks of 128 protos

#define BM 64                      // CTA rows
#define BN 128                     // CTA cols
#define NTK (D_DIM / 16)           // 32 k16 tiles
#define NTP (P_ROWS / 16)          // 256 n16 (tile-pair) blocks
#define NMT (B_ROWS / 16)          // 512 m16 tiles

#define OFF_PSQ  0                 // 128 floats
#define OFF_PLAB 512               // 128 ints
#define OFF_C    1024
#define CPITCH 132                 // epilogue C smem pitch (floats)
#define EPI_BYTES (64 * CPITCH * 4)                      // 33792
#define SMEM_TOTAL (OFF_C + EPI_BYTES)                   // 34816 -> 3 CTAs/SM

// ===========================================================================
// Scratch (allocation-free)
// A in mma A-fragment order: [mt (512)][tk (32)][lane (32)] x uint4 (a0..a3)
// B in mma B-fragment order: [tk (32)][tp (256)][lane (32)] x uint4
//   uint4 = {tile 2tp: b0, b1, tile 2tp+1: b0, b1}
// ===========================================================================
__device__ uint4 g_Afrag[NMT * NTK * 32];
__device__ uint4 g_Bfrag[NTK * NTP * 32];
__device__ float g_fsq[B_ROWS];
__device__ float g_psq[P_ROWS];
__device__ float g_pmd[NCHUNK * B_ROWS];
__device__ float g_psd[NCHUNK * B_ROWS];
__device__ float g_pmn[NCHUNK * B_ROWS];
__device__ float g_psn[NCHUNK * B_ROWS];

#define MMA16816(c, a, b0, b1)                                                  \
    asm volatile("mma.sync.aligned.m16n8k16.row.col.f32.f16.f16.f32 "           \
        "{%0,%1,%2,%3}, {%4,%5,%6,%7}, {%8,%9}, {%0,%1,%2,%3};"                 \
        : "+f"((c)[0]), "+f"((c)[1]), "+f"((c)[2]), "+f"((c)[3])                \
        : "r"((a).x), "r"((a).y), "r"((a).z), "r"((a).w),                       \
          "r"(b0), "r"(b1))

// ===========================================================================
// Kernel 1 (R10 version — fastest measured): fp16 quantize + squared norms
// OF THE QUANTIZED vectors, writing both operands in mma fragment order.
// One warp per row, float2 loads.
// ===========================================================================
__global__ void prep_kernel(const float* __restrict__ feat,
                            const float* __restrict__ proto) {
    int warp = (blockIdx.x * blockDim.x + threadIdx.x) >> 5;
    int lane = threadIdx.x & 31;
    if (warp >= B_ROWS + P_ROWS) return;
    bool isA = warp < B_ROWS;
    int row = isA ? warp : warp - B_ROWS;
    const float* src = (isA ? feat : proto) + (size_t)row * D_DIM;

    float s = 0.f;
    if (isA) {
        uint32_t* dst = (uint32_t*)g_Afrag;
        int mt = row >> 4;
        int tr = row & 15;
        int rsel = (tr >> 3) & 1;            // a0/a1 select
        int lane_base = (tr & 7) * 4;
#pragma unroll
        for (int t = 0; t < 8; t++) {
            int k = t * 64 + lane * 2;
            float2 v = *(const float2*)(src + k);
            __half h0 = __float2half_rn(v.x);
            __half h1 = __float2half_rn(v.y);
            float q0 = __half2float(h0), q1 = __half2float(h1);
            s = fmaf(q0, q0, fmaf(q1, q1, s));
            uint32_t pack = (uint32_t)__half_as_ushort(h0)
                          | ((uint32_t)__half_as_ushort(h1) << 16);
            int tk = k >> 4;
            int kk = k & 15;
            int reg = rsel + ((kk >> 3) << 1);
            int lane_t = lane_base + ((kk & 7) >> 1);
            uint32_t idx = (uint32_t)(((mt * NTK + tk) * 32 + lane_t) * 4 + reg);
            dst[idx] = pack;
        }
    } else {
        uint32_t* dst = (uint32_t*)g_Bfrag;
        int pr = row & 7;            // n' within n8 tile
        int tp = row >> 4;           // tile-pair index
        int sub = (row >> 3) & 1;    // which tile of the pair
#pragma unroll
        for (int t = 0; t < 8; t++) {
            int k = t * 64 + lane * 2;
            float2 v = *(const float2*)(src + k);
            __half h0 = __float2half_rn(v.x);
            __half h1 = __float2half_rn(v.y);
            float q0 = __half2float(h0), q1 = __half2float(h1);
            s = fmaf(q0, q0, fmaf(q1, q1, s));
            uint32_t pack = (uint32_t)__half_as_ushort(h0)
                          | ((uint32_t)__half_as_ushort(h1) << 16);
            uint32_t idx = (uint32_t)((((k >> 4) * NTP + tp) * 32
                          + pr * 4 + ((k & 7) >> 1)) * 4
                          + sub * 2 + ((k >> 3) & 1));
            dst[idx] = pack;
        }
    }
#pragma unroll
    for (int m = 16; m; m >>= 1) s += __shfl_xor_sync(0xffffffffu, s, m);
    if (lane == 0) {
        if (isA) g_fsq[row] = s; else g_psq[row] = s;
    }
}

// ===========================================================================
// Kernel 2: pure LDG->mma.sync mainloop, 32x32 warp tiles for 3 CTAs/SM.
// grid = (32 n-chunks, 128 m-tiles), 256 threads = 2(wm) x 4(wn) warps.
// Warp tile: 2 m16 x 2 tile-pairs (32 rows x 32 cols), acc = 32 regs.
// ===========================================================================
__global__ __launch_bounds__(256, 3) void dce_mma_kernel(
    const int* __restrict__ label, const int* __restrict__ plab) {
    extern __shared__ __align__(1024) char smem[];
    float* psq_s = (float*)(smem + OFF_PSQ);
    int* plab_s = (int*)(smem + OFF_PLAB);

    const int tid = threadIdx.x;
    const int lane = tid & 31;
    const int wid = tid >> 5;
    const int wm = wid >> 2;       // 0..1
    const int wn = wid & 3;        // 0..3
    const int m0 = blockIdx.y * BM;
    const int n0 = blockIdx.x * BN;
    const int mt0 = (m0 >> 4) + wm * 2;    // this warp's 2 m16 tiles
    const int tp0 = (n0 >> 4) + wn * 2;    // this warp's 2 tile-pairs

    if (tid < 128) {
        psq_s[tid] = g_psq[n0 + tid];
        plab_s[tid] = plab[n0 + tid];
    }

    float acc[2][4][4];
#pragma unroll
    for (int i = 0; i < 2; i++)
#pragma unroll
        for (int j = 0; j < 4; j++)
#pragma unroll
            for (int q = 0; q < 4; q++) acc[i][j][q] = 0.f;

    const uint4* __restrict__ Af = g_Afrag;
    const uint4* __restrict__ Bf = g_Bfrag;

    uint4 a[2][2], b[2][2];
    // preload tk = 0
#pragma unroll
    for (int mt = 0; mt < 2; mt++)
        a[0][mt] = Af[((size_t)(mt0 + mt) * NTK + 0) * 32 + lane];
    b[0][0] = Bf[((size_t)0 * NTP + tp0) * 32 + lane];
    b[0][1] = Bf[((size_t)0 * NTP + tp0 + 1) * 32 + lane];

#pragma unroll 4
    for (int tk = 0; tk < NTK; tk++) {
        int cur = tk & 1, nxt = cur ^ 1;
        if (tk + 1 < NTK) {
#pragma unroll
            for (int mt = 0; mt < 2; mt++)
                a[nxt][mt] = Af[((size_t)(mt0 + mt) * NTK + tk + 1) * 32 + lane];
            b[nxt][0] = Bf[((size_t)(tk + 1) * NTP + tp0) * 32 + lane];
            b[nxt][1] = Bf[((size_t)(tk + 1) * NTP + tp0 + 1) * 32 + lane];
        }
#pragma unroll
        for (int mt = 0; mt < 2; mt++) {
            MMA16816(acc[mt][0], a[cur][mt], b[cur][0].x, b[cur][0].y);
            MMA16816(acc[mt][1], a[cur][mt], b[cur][0].z, b[cur][0].w);
            MMA16816(acc[mt][2], a[cur][mt], b[cur][1].x, b[cur][1].y);
            MMA16816(acc[mt][3], a[cur][mt], b[cur][1].z, b[cur][1].w);
        }
    }

    __syncthreads();   // psq_s/plab_s visible + everyone ready for C dump

    // --- dump accumulators to SMEM (64 rows x 128 cols) ---
    float* Cs = (float*)(smem + OFF_C);
#pragma unroll
    for (int mt = 0; mt < 2; mt++)
#pragma unroll
        for (int nt = 0; nt < 4; nt++) {
            int r = wm * 32 + mt * 16 + (lane >> 2);
            int c = wn * 32 + nt * 8 + ((lane & 3) << 1);
            Cs[r * CPITCH + c] = acc[mt][nt][0];
            Cs[r * CPITCH + c + 1] = acc[mt][nt][1];
            Cs[(r + 8) * CPITCH + c] = acc[mt][nt][2];
            Cs[(r + 8) * CPITCH + c + 1] = acc[mt][nt][3];
        }
    __syncthreads();

    // --- dual online LSE: 4 threads per row (32 cols each), 2-round merge
    int row = tid >> 2;
    int qt = tid & 3;
    int c0 = qt * 32;
    float fsq = g_fsq[m0 + row];
    int lab = label[m0 + row];
    float md = -INFINITY, mn = -INFINITY;
#pragma unroll 4
    for (int j = 0; j < 32; j++) {
        int col = c0 + j;
        float dot = Cs[row * CPITCH + col];
        float d2 = fmaxf(fsq + psq_s[col] - 2.0f * dot, 0.0f);
        float lg = -d2;
        Cs[row * CPITCH + col] = lg;
        md = fmaxf(md, lg);
        if (plab_s[col] == lab) mn = fmaxf(mn, lg);
    }
    float sd = 0.f, sn = 0.f;
#pragma unroll 4
    for (int j = 0; j < 32; j++) {
        int col = c0 + j;
        float lg = Cs[row * CPITCH + col];
        sd += __expf(lg - md);
        if (plab_s[col] == lab) sn += __expf(lg - mn);
    }
    // merge 4 quarter-partials (threads tid^1, tid^2: same warp)
#pragma unroll
    for (int mshift = 1; mshift <= 2; mshift <<= 1) {
        float md2 = __shfl_xor_sync(0xffffffffu, md, mshift);
        float sd2 = __shfl_xor_sync(0xffffffffu, sd, mshift);
        float mn2 = __shfl_xor_sync(0xffffffffu, mn, mshift);
        float sn2 = __shfl_xor_sync(0xffffffffu, sn, mshift);
        float M = fmaxf(md, md2);
        sd = sd * __expf(md - M) + sd2 * __expf(md2 - M);
        md = M;
        float Mn = fmaxf(mn, mn2);
        float f0 = (mn == -INFINITY) ? 0.f : __expf(mn - Mn);
        float f1 = (mn2 == -INFINITY) ? 0.f : __expf(mn2 - Mn);
        sn = sn * f0 + sn2 * f1;
        mn = Mn;
    }
    if (qt == 0) {
        size_t o = (size_t)blockIdx.x * B_ROWS + m0 + row;
        g_pmd[o] = md;
        g_psd[o] = sd;
        g_pmn[o] = mn;
        g_psn[o] = sn;
    }
}

// ===========================================================================
// Kernel 3: combine 32 chunk-partials per row -> loss. Two independent
// LSE chains (halved dependent-latency), merged at the end.
// ===========================================================================
__global__ void combine_kernel(float* __restrict__ out) {
    int r = blockIdx.x * blockDim.x + threadIdx.x;
    if (r >= B_ROWS) return;
    float md[2] = {-INFINITY, -INFINITY}, sd[2] = {0.f, 0.f};
    float mn[2] = {-INFINITY, -INFINITY}, sn[2] = {0.f, 0.f};
#pragma unroll
    for (int h = 0; h < 2; h++) {
        for (int c = h * 16; c < h * 16 + 16; c++) {
            size_t o = (size_t)c * B_ROWS + r;
            float m2 = g_pmd[o], s2 = g_psd[o];
            float M = fmaxf(md[h], m2);
            sd[h] = sd[h] * __expf(md[h] - M) + s2 * __expf(m2 - M);
            md[h] = M;
            float mm = g_pmn[o], ss = g_psn[o];
            float Mn = fmaxf(mn[h], mm);
            float f0 = (mn[h] == -INFINITY) ? 0.f : __expf(mn[h] - Mn);
            float f1 = (mm == -INFINITY) ? 0.f : __expf(mm - Mn);
            sn[h] = sn[h] * f0 + ss * f1;
            mn[h] = Mn;
        }
    }
    float M = fmaxf(md[0], md[1]);
    float SD = sd[0] * __expf(md[0] - M) + sd[1] * __expf(md[1] - M);
    float Mn = fmaxf(mn[0], mn[1]);
    float f0 = (mn[0] == -INFINITY) ? 0.f : __expf(mn[0] - Mn);
    float f1 = (mn[1] == -INFINITY) ? 0.f : __expf(mn[1] - Mn);
    float SN = sn[0] * f0 + sn[1] * f1;
    out[r] = (M + logf(SD)) - (Mn + logf(SN));
}

// ===========================================================================
// Launch
// ===========================================================================
extern "C" void kernel_launch(void* const* d_in, const int* in_sizes, int n_in,
                              void* d_out, int out_size) {
    const float* feature = (const float*)d_in[0];
    const int* label = (const int*)d_in[1];
    const float* proto = (const float*)d_in[2];
    const int* plab = (const int*)d_in[3];
    float* out = (float*)d_out;

    cudaFuncSetAttribute(dce_mma_kernel, cudaFuncAttributeMaxDynamicSharedMemorySize,
                         SMEM_TOTAL);

    int warps = B_ROWS + P_ROWS;
    prep_kernel<<<(warps * 32 + 255) / 256, 256>>>(feature, proto);

    dim3 grid(P_ROWS / BN, B_ROWS / BM);
    dce_mma_kernel<<<grid, 256, SMEM_TOTAL>>>(label, plab);

    combine_kernel<<<(B_ROWS + 255) / 256, 256>>>(out);
}

// round 15
// speedup vs baseline: 1.5043x; 1.5043x over previous
#include <cuda_runtime.h>
#include <cuda_fp16.h>
#include <math.h>
#include <stdint.h>

// ===========================================================================
// Problem constants
// ===========================================================================
#define B_ROWS 8192
#define P_ROWS 4096
#define D_DIM  512
#define NCHUNK (P_ROWS / 128)     // 32 column chunks of 128 protos

#define BM 128
#define BN 128
#define NTK (D_DIM / 16)           // 32 k16 tiles
#define NTP (P_ROWS / 16)          // 256 n16 (tile-pair) blocks
#define NMT (B_ROWS / 16)          // 512 m16 tiles

// ===========================================================================
// Scratch (allocation-free)
// A in mma A-fragment order: [mt (512)][tk (32)][lane (32)] x uint4 (a0..a3)
// B in mma B-fragment order: [tk (32)][tp (256)][lane (32)] x uint4
//   uint4 = {tile 2tp: b0, b1, tile 2tp+1: b0, b1}
// ===========================================================================
__device__ uint4 g_Afrag[NMT * NTK * 32];
__device__ uint4 g_Bfrag[NTK * NTP * 32];
__device__ float g_fsq[B_ROWS];
__device__ float g_psq[P_ROWS];
__device__ float g_pmd[NCHUNK * B_ROWS];
__device__ float g_psd[NCHUNK * B_ROWS];
__device__ float g_pmn[NCHUNK * B_ROWS];
__device__ float g_psn[NCHUNK * B_ROWS];

#define MMA16816(c, a, b0, b1)                                                  \
    asm volatile("mma.sync.aligned.m16n8k16.row.col.f32.f16.f16.f32 "           \
        "{%0,%1,%2,%3}, {%4,%5,%6,%7}, {%8,%9}, {%0,%1,%2,%3};"                 \
        : "+f"((c)[0]), "+f"((c)[1]), "+f"((c)[2]), "+f"((c)[3])                \
        : "r"((a).x), "r"((a).y), "r"((a).z), "r"((a).w),                       \
          "r"(b0), "r"(b1))

// ===========================================================================
// Kernel 1 (R10 version — fastest measured): fp16 quantize + squared norms
// OF THE QUANTIZED vectors, writing both operands in mma fragment order.
// One warp per row, float2 loads.
// ===========================================================================
__global__ void prep_kernel(const float* __restrict__ feat,
                            const float* __restrict__ proto) {
    int warp = (blockIdx.x * blockDim.x + threadIdx.x) >> 5;
    int lane = threadIdx.x & 31;
    if (warp >= B_ROWS + P_ROWS) return;
    bool isA = warp < B_ROWS;
    int row = isA ? warp : warp - B_ROWS;
    const float* src = (isA ? feat : proto) + (size_t)row * D_DIM;

    float s = 0.f;
    if (isA) {
        uint32_t* dst = (uint32_t*)g_Afrag;
        int mt = row >> 4;
        int tr = row & 15;
        int rsel = (tr >> 3) & 1;            // a0/a1 select
        int lane_base = (tr & 7) * 4;
#pragma unroll
        for (int t = 0; t < 8; t++) {
            int k = t * 64 + lane * 2;
            float2 v = *(const float2*)(src + k);
            __half h0 = __float2half_rn(v.x);
            __half h1 = __float2half_rn(v.y);
            float q0 = __half2float(h0), q1 = __half2float(h1);
            s = fmaf(q0, q0, fmaf(q1, q1, s));
            uint32_t pack = (uint32_t)__half_as_ushort(h0)
                          | ((uint32_t)__half_as_ushort(h1) << 16);
            int tk = k >> 4;
            int kk = k & 15;
            int reg = rsel + ((kk >> 3) << 1);
            int lane_t = lane_base + ((kk & 7) >> 1);
            uint32_t idx = (uint32_t)(((mt * NTK + tk) * 32 + lane_t) * 4 + reg);
            dst[idx] = pack;
        }
    } else {
        uint32_t* dst = (uint32_t*)g_Bfrag;
        int pr = row & 7;            // n' within n8 tile
        int tp = row >> 4;           // tile-pair index
        int sub = (row >> 3) & 1;    // which tile of the pair
#pragma unroll
        for (int t = 0; t < 8; t++) {
            int k = t * 64 + lane * 2;
            float2 v = *(const float2*)(src + k);
            __half h0 = __float2half_rn(v.x);
            __half h1 = __float2half_rn(v.y);
            float q0 = __half2float(h0), q1 = __half2float(h1);
            s = fmaf(q0, q0, fmaf(q1, q1, s));
            uint32_t pack = (uint32_t)__half_as_ushort(h0)
                          | ((uint32_t)__half_as_ushort(h1) << 16);
            uint32_t idx = (uint32_t)((((k >> 4) * NTP + tp) * 32
                          + pr * 4 + ((k & 7) >> 1)) * 4
                          + sub * 2 + ((k >> 3) & 1));
            dst[idx] = pack;
        }
    }
#pragma unroll
    for (int m = 16; m; m >>= 1) s += __shfl_xor_sync(0xffffffffu, s, m);
    if (lane == 0) {
        if (isA) g_fsq[row] = s; else g_psq[row] = s;
    }
}

// ===========================================================================
// Kernel 2: pure LDG->mma.sync mainloop (R10 champion, L1-traffic-optimal
// 64x32 warp tile, occ 2) + IN-REGISTER epilogue: dual-LSE partials computed
// straight from acc fragments, quad-lane shuffle merge, 8KB smem exchange.
// grid = (32 n-chunks, 64 m-tiles), 256 threads = 2(m) x 4(n) warps.
// ===========================================================================
__global__ __launch_bounds__(256, 2) void dce_mma_kernel(
    const int* __restrict__ label, const int* __restrict__ plab) {
    __shared__ float psq_s[128];
    __shared__ int plab_s[128];
    __shared__ float4 part[128][4];          // [row][wn] partials (8KB)

    const int tid = threadIdx.x;
    const int lane = tid & 31;
    const int wid = tid >> 5;
    const int wm = wid >> 2;       // 0..1
    const int wn = wid & 3;        // 0..3
    const int m0 = blockIdx.y * BM;
    const int n0 = blockIdx.x * BN;
    const int mt0 = (m0 >> 4) + wm * 4;    // first of this warp's 4 m16 tiles
    const int tp0 = (n0 >> 4) + wn * 2;    // first of this warp's 2 tile-pairs

    if (tid < 128) {
        psq_s[tid] = g_psq[n0 + tid];
        plab_s[tid] = plab[n0 + tid];
    }

    float acc[4][4][4];
#pragma unroll
    for (int i = 0; i < 4; i++)
#pragma unroll
        for (int j = 0; j < 4; j++)
#pragma unroll
            for (int q = 0; q < 4; q++) acc[i][j][q] = 0.f;

    const uint4* __restrict__ Af = g_Afrag;
    const uint4* __restrict__ Bf = g_Bfrag;

    uint4 a[2][4], b[2][2];
    // preload tk = 0
#pragma unroll
    for (int mt = 0; mt < 4; mt++)
        a[0][mt] = Af[((size_t)(mt0 + mt) * NTK + 0) * 32 + lane];
    b[0][0] = Bf[((size_t)0 * NTP + tp0) * 32 + lane];
    b[0][1] = Bf[((size_t)0 * NTP + tp0 + 1) * 32 + lane];

#pragma unroll 2
    for (int tk = 0; tk < NTK; tk++) {
        int cur = tk & 1, nxt = cur ^ 1;
        if (tk + 1 < NTK) {
#pragma unroll
            for (int mt = 0; mt < 4; mt++)
                a[nxt][mt] = Af[((size_t)(mt0 + mt) * NTK + tk + 1) * 32 + lane];
            b[nxt][0] = Bf[((size_t)(tk + 1) * NTP + tp0) * 32 + lane];
            b[nxt][1] = Bf[((size_t)(tk + 1) * NTP + tp0 + 1) * 32 + lane];
        }
#pragma unroll
        for (int mt = 0; mt < 4; mt++) {
            MMA16816(acc[mt][0], a[cur][mt], b[cur][0].x, b[cur][0].y);
            MMA16816(acc[mt][1], a[cur][mt], b[cur][0].z, b[cur][0].w);
            MMA16816(acc[mt][2], a[cur][mt], b[cur][1].x, b[cur][1].y);
            MMA16816(acc[mt][3], a[cur][mt], b[cur][1].z, b[cur][1].w);
        }
    }

    __syncthreads();   // psq_s/plab_s visible

    // --- in-register epilogue: 8 row-instances per thread (4mt x 2 row-halves)
    // C fragment: row = (lane>>2) + 8*rh, col = (lane&3)*2 + h; val acc[mt][nt][rh*2+h]
#pragma unroll
    for (int mt = 0; mt < 4; mt++) {
#pragma unroll
        for (int rh = 0; rh < 2; rh++) {
            int rloc = wm * 64 + mt * 16 + rh * 8 + (lane >> 2);
            int r = m0 + rloc;
            float fsq = g_fsq[r];
            int lab = label[r];
            float lg[8];
            float md = -INFINITY, mn = -INFINITY;
#pragma unroll
            for (int nt = 0; nt < 4; nt++) {
#pragma unroll
                for (int h = 0; h < 2; h++) {
                    int col = wn * 32 + nt * 8 + ((lane & 3) << 1) + h;
                    float dot = acc[mt][nt][rh * 2 + h];
                    float d2 = fmaxf(fsq + psq_s[col] - 2.0f * dot, 0.0f);
                    float l = -d2;
                    lg[nt * 2 + h] = l;
                    md = fmaxf(md, l);
                    if (plab_s[col] == lab) mn = fmaxf(mn, l);
                }
            }
            float sd = 0.f, sn = 0.f;
#pragma unroll
            for (int nt = 0; nt < 4; nt++) {
#pragma unroll
                for (int h = 0; h < 2; h++) {
                    int col = wn * 32 + nt * 8 + ((lane & 3) << 1) + h;
                    float l = lg[nt * 2 + h];
                    sd += __expf(l - md);
                    if (plab_s[col] == lab) sn += __expf(l - mn);
                }
            }
            // merge across the 4 quad lanes (same row, different cols)
#pragma unroll
            for (int ms = 1; ms <= 2; ms <<= 1) {
                float md2 = __shfl_xor_sync(0xffffffffu, md, ms);
                float sd2 = __shfl_xor_sync(0xffffffffu, sd, ms);
                float mn2 = __shfl_xor_sync(0xffffffffu, mn, ms);
                float sn2 = __shfl_xor_sync(0xffffffffu, sn, ms);
                float M = fmaxf(md, md2);
                sd = sd * __expf(md - M) + sd2 * __expf(md2 - M);
                md = M;
                float Mn = fmaxf(mn, mn2);
                float f0 = (mn == -INFINITY) ? 0.f : __expf(mn - Mn);
                float f1 = (mn2 == -INFINITY) ? 0.f : __expf(mn2 - Mn);
                sn = sn * f0 + sn2 * f1;
                mn = Mn;
            }
            if ((lane & 3) == 0)
                part[rloc][wn] = make_float4(md, sd, mn, sn);
        }
    }
    __syncthreads();

    // --- final per-row merge of the 4 warp partials; write global partials
    if (tid < 128) {
        float4 p = part[tid][0];
        float md = p.x, sd = p.y, mn = p.z, sn = p.w;
#pragma unroll
        for (int w = 1; w < 4; w++) {
            float4 q = part[tid][w];
            float M = fmaxf(md, q.x);
            sd = sd * __expf(md - M) + q.y * __expf(q.x - M);
            md = M;
            float Mn = fmaxf(mn, q.z);
            float f0 = (mn == -INFINITY) ? 0.f : __expf(mn - Mn);
            float f1 = (q.z == -INFINITY) ? 0.f : __expf(q.z - Mn);
            sn = sn * f0 + q.w * f1;
            mn = Mn;
        }
        size_t o = (size_t)blockIdx.x * B_ROWS + m0 + tid;
        g_pmd[o] = md;
        g_psd[o] = sd;
        g_pmn[o] = mn;
        g_psn[o] = sn;
    }
}

// ===========================================================================
// Kernel 3: combine 32 chunk-partials per row -> loss. Two independent
// LSE chains (halved dependent-latency), merged at the end.
// ===========================================================================
__global__ void combine_kernel(float* __restrict__ out) {
    int r = blockIdx.x * blockDim.x + threadIdx.x;
    if (r >= B_ROWS) return;
    float md[2] = {-INFINITY, -INFINITY}, sd[2] = {0.f, 0.f};
    float mn[2] = {-INFINITY, -INFINITY}, sn[2] = {0.f, 0.f};
#pragma unroll
    for (int h = 0; h < 2; h++) {
        for (int c = h * 16; c < h * 16 + 16; c++) {
            size_t o = (size_t)c * B_ROWS + r;
            float m2 = g_pmd[o], s2 = g_psd[o];
            float M = fmaxf(md[h], m2);
            sd[h] = sd[h] * __expf(md[h] - M) + s2 * __expf(m2 - M);
            md[h] = M;
            float mm = g_pmn[o], ss = g_psn[o];
            float Mn = fmaxf(mn[h], mm);
            float f0 = (mn[h] == -INFINITY) ? 0.f : __expf(mn[h] - Mn);
            float f1 = (mm == -INFINITY) ? 0.f : __expf(mm - Mn);
            sn[h] = sn[h] * f0 + ss * f1;
            mn[h] = Mn;
        }
    }
    float M = fmaxf(md[0], md[1]);
    float SD = sd[0] * __expf(md[0] - M) + sd[1] * __expf(md[1] - M);
    float Mn = fmaxf(mn[0], mn[1]);
    float f0 = (mn[0] == -INFINITY) ? 0.f : __expf(mn[0] - Mn);
    float f1 = (mn[1] == -INFINITY) ? 0.f : __expf(mn[1] - Mn);
    float SN = sn[0] * f0 + sn[1] * f1;
    out[r] = (M + logf(SD)) - (Mn + logf(SN));
}

// ===========================================================================
// Launch
// ===========================================================================
extern "C" void kernel_launch(void* const* d_in, const int* in_sizes, int n_in,
                              void* d_out, int out_size) {
    const float* feature = (const float*)d_in[0];
    const int* label = (const int*)d_in[1];
    const float* proto = (const float*)d_in[2];
    const int* plab = (const int*)d_in[3];
    float* out = (float*)d_out;

    int warps = B_ROWS + P_ROWS;
    prep_kernel<<<(warps * 32 + 255) / 256, 256>>>(feature, proto);

    dim3 grid(P_ROWS / BN, B_ROWS / BM);
    dce_mma_kernel<<<grid, 256>>>(label, plab);

    combine_kernel<<<(B_ROWS + 255) / 256, 256>>>(out);
}

// round 16
// speedup vs baseline: 1.5047x; 1.0003x over previous
#include <cuda_runtime.h>
#include <cuda_fp16.h>
#include <math.h>
#include <stdint.h>

// ===========================================================================
// Problem constants
// ===========================================================================
#define B_ROWS 8192
#define P_ROWS 4096
#define D_DIM  512
#define NCHUNK (P_ROWS / 128)     // 32 column chunks of 128 protos

#define BM 128
#define BN 128
#define NTK (D_DIM / 16)           // 32 k16 tiles
#define NTP (P_ROWS / 16)          // 256 n16 (tile-pair) blocks
#define NMT (B_ROWS / 16)          // 512 m16 tiles

// ===========================================================================
// Scratch (allocation-free)
// A in mma A-fragment order: [mt (512)][tk (32)][lane (32)] x uint4 (a0..a3)
// B in mma B-fragment order: [tk (32)][tp (256)][lane (32)] x uint4
//   uint4 = {tile 2tp: b0, b1, tile 2tp+1: b0, b1}
// ===========================================================================
__device__ uint4 g_Afrag[NMT * NTK * 32];
__device__ uint4 g_Bfrag[NTK * NTP * 32];
__device__ float g_fsq[B_ROWS];
__device__ float g_psq[P_ROWS];
__device__ float g_pmd[NCHUNK * B_ROWS];
__device__ float g_psd[NCHUNK * B_ROWS];
__device__ float g_pmn[NCHUNK * B_ROWS];
__device__ float g_psn[NCHUNK * B_ROWS];

#define MMA16816(c, a, b0, b1)                                                  \
    asm volatile("mma.sync.aligned.m16n8k16.row.col.f32.f16.f16.f32 "           \
        "{%0,%1,%2,%3}, {%4,%5,%6,%7}, {%8,%9}, {%0,%1,%2,%3};"                 \
        : "+f"((c)[0]), "+f"((c)[1]), "+f"((c)[2]), "+f"((c)[3])                \
        : "r"((a).x), "r"((a).y), "r"((a).z), "r"((a).w),                       \
          "r"(b0), "r"(b1))

// ===========================================================================
// Kernel 1 (R10 version — fastest measured): fp16 quantize + squared norms
// OF THE QUANTIZED vectors, writing both operands in mma fragment order.
// One warp per row, float2 loads.
// ===========================================================================
__global__ void prep_kernel(const float* __restrict__ feat,
                            const float* __restrict__ proto) {
    int warp = (blockIdx.x * blockDim.x + threadIdx.x) >> 5;
    int lane = threadIdx.x & 31;
    if (warp >= B_ROWS + P_ROWS) return;
    bool isA = warp < B_ROWS;
    int row = isA ? warp : warp - B_ROWS;
    const float* src = (isA ? feat : proto) + (size_t)row * D_DIM;

    float s = 0.f;
    if (isA) {
        uint32_t* dst = (uint32_t*)g_Afrag;
        int mt = row >> 4;
        int tr = row & 15;
        int rsel = (tr >> 3) & 1;            // a0/a1 select
        int lane_base = (tr & 7) * 4;
#pragma unroll
        for (int t = 0; t < 8; t++) {
            int k = t * 64 + lane * 2;
            float2 v = *(const float2*)(src + k);
            __half h0 = __float2half_rn(v.x);
            __half h1 = __float2half_rn(v.y);
            float q0 = __half2float(h0), q1 = __half2float(h1);
            s = fmaf(q0, q0, fmaf(q1, q1, s));
            uint32_t pack = (uint32_t)__half_as_ushort(h0)
                          | ((uint32_t)__half_as_ushort(h1) << 16);
            int tk = k >> 4;
            int kk = k & 15;
            int reg = rsel + ((kk >> 3) << 1);
            int lane_t = lane_base + ((kk & 7) >> 1);
            uint32_t idx = (uint32_t)(((mt * NTK + tk) * 32 + lane_t) * 4 + reg);
            dst[idx] = pack;
        }
    } else {
        uint32_t* dst = (uint32_t*)g_Bfrag;
        int pr = row & 7;            // n' within n8 tile
        int tp = row >> 4;           // tile-pair index
        int sub = (row >> 3) & 1;    // which tile of the pair
#pragma unroll
        for (int t = 0; t < 8; t++) {
            int k = t * 64 + lane * 2;
            float2 v = *(const float2*)(src + k);
            __half h0 = __float2half_rn(v.x);
            __half h1 = __float2half_rn(v.y);
            float q0 = __half2float(h0), q1 = __half2float(h1);
            s = fmaf(q0, q0, fmaf(q1, q1, s));
            uint32_t pack = (uint32_t)__half_as_ushort(h0)
                          | ((uint32_t)__half_as_ushort(h1) << 16);
            uint32_t idx = (uint32_t)((((k >> 4) * NTP + tp) * 32
                          + pr * 4 + ((k & 7) >> 1)) * 4
                          + sub * 2 + ((k >> 3) & 1));
            dst[idx] = pack;
        }
    }
#pragma unroll
    for (int m = 16; m; m >>= 1) s += __shfl_xor_sync(0xffffffffu, s, m);
    if (lane == 0) {
        if (isA) g_fsq[row] = s; else g_psq[row] = s;
    }
}

// ===========================================================================
// Kernel 2: pure LDG->mma.sync mainloop (R10 champion, L1-traffic-optimal
// 64x32 warp tile, occ 2) + IN-REGISTER epilogue: dual-LSE partials computed
// straight from acc fragments, quad-lane shuffle merge, 8KB smem exchange.
// grid = (32 n-chunks, 64 m-tiles), 256 threads = 2(m) x 4(n) warps.
// ===========================================================================
__global__ __launch_bounds__(256, 2) void dce_mma_kernel(
    const int* __restrict__ label, const int* __restrict__ plab) {
    __shared__ float psq_s[128];
    __shared__ int plab_s[128];
    __shared__ float4 part[128][4];          // [row][wn] partials (8KB)

    const int tid = threadIdx.x;
    const int lane = tid & 31;
    const int wid = tid >> 5;
    const int wm = wid >> 2;       // 0..1
    const int wn = wid & 3;        // 0..3
    const int m0 = blockIdx.y * BM;
    const int n0 = blockIdx.x * BN;
    const int mt0 = (m0 >> 4) + wm * 4;    // first of this warp's 4 m16 tiles
    const int tp0 = (n0 >> 4) + wn * 2;    // first of this warp's 2 tile-pairs

    if (tid < 128) {
        psq_s[tid] = g_psq[n0 + tid];
        plab_s[tid] = plab[n0 + tid];
    }

    float acc[4][4][4];
#pragma unroll
    for (int i = 0; i < 4; i++)
#pragma unroll
        for (int j = 0; j < 4; j++)
#pragma unroll
            for (int q = 0; q < 4; q++) acc[i][j][q] = 0.f;

    const uint4* __restrict__ Af = g_Afrag;
    const uint4* __restrict__ Bf = g_Bfrag;

    uint4 a[2][4], b[2][2];
    // preload tk = 0
#pragma unroll
    for (int mt = 0; mt < 4; mt++)
        a[0][mt] = Af[((size_t)(mt0 + mt) * NTK + 0) * 32 + lane];
    b[0][0] = Bf[((size_t)0 * NTP + tp0) * 32 + lane];
    b[0][1] = Bf[((size_t)0 * NTP + tp0 + 1) * 32 + lane];

#pragma unroll 2
    for (int tk = 0; tk < NTK; tk++) {
        int cur = tk & 1, nxt = cur ^ 1;
        if (tk + 1 < NTK) {
#pragma unroll
            for (int mt = 0; mt < 4; mt++)
                a[nxt][mt] = Af[((size_t)(mt0 + mt) * NTK + tk + 1) * 32 + lane];
            b[nxt][0] = Bf[((size_t)(tk + 1) * NTP + tp0) * 32 + lane];
            b[nxt][1] = Bf[((size_t)(tk + 1) * NTP + tp0 + 1) * 32 + lane];
        }
#pragma unroll
        for (int mt = 0; mt < 4; mt++) {
            MMA16816(acc[mt][0], a[cur][mt], b[cur][0].x, b[cur][0].y);
            MMA16816(acc[mt][1], a[cur][mt], b[cur][0].z, b[cur][0].w);
            MMA16816(acc[mt][2], a[cur][mt], b[cur][1].x, b[cur][1].y);
            MMA16816(acc[mt][3], a[cur][mt], b[cur][1].z, b[cur][1].w);
        }
    }

    __syncthreads();   // psq_s/plab_s visible

    // --- in-register epilogue: 8 row-instances per thread (4mt x 2 row-halves)
    // C fragment: row = (lane>>2) + 8*rh, col = (lane&3)*2 + h; val acc[mt][nt][rh*2+h]
#pragma unroll
    for (int mt = 0; mt < 4; mt++) {
#pragma unroll
        for (int rh = 0; rh < 2; rh++) {
            int rloc = wm * 64 + mt * 16 + rh * 8 + (lane >> 2);
            int r = m0 + rloc;
            float fsq = g_fsq[r];
            int lab = label[r];
            float lg[8];
            float md = -INFINITY, mn = -INFINITY;
#pragma unroll
            for (int nt = 0; nt < 4; nt++) {
#pragma unroll
                for (int h = 0; h < 2; h++) {
                    int col = wn * 32 + nt * 8 + ((lane & 3) << 1) + h;
                    float dot = acc[mt][nt][rh * 2 + h];
                    float d2 = fmaxf(fsq + psq_s[col] - 2.0f * dot, 0.0f);
                    float l = -d2;
                    lg[nt * 2 + h] = l;
                    md = fmaxf(md, l);
                    if (plab_s[col] == lab) mn = fmaxf(mn, l);
                }
            }
            float sd = 0.f, sn = 0.f;
#pragma unroll
            for (int nt = 0; nt < 4; nt++) {
#pragma unroll
                for (int h = 0; h < 2; h++) {
                    int col = wn * 32 + nt * 8 + ((lane & 3) << 1) + h;
                    float l = lg[nt * 2 + h];
                    sd += __expf(l - md);
                    if (plab_s[col] == lab) sn += __expf(l - mn);
                }
            }
            // merge across the 4 quad lanes (same row, different cols)
#pragma unroll
            for (int ms = 1; ms <= 2; ms <<= 1) {
                float md2 = __shfl_xor_sync(0xffffffffu, md, ms);
                float sd2 = __shfl_xor_sync(0xffffffffu, sd, ms);
                float mn2 = __shfl_xor_sync(0xffffffffu, mn, ms);
                float sn2 = __shfl_xor_sync(0xffffffffu, sn, ms);
                float M = fmaxf(md, md2);
                sd = sd * __expf(md - M) + sd2 * __expf(md2 - M);
                md = M;
                float Mn = fmaxf(mn, mn2);
                float f0 = (mn == -INFINITY) ? 0.f : __expf(mn - Mn);
                float f1 = (mn2 == -INFINITY) ? 0.f : __expf(mn2 - Mn);
                sn = sn * f0 + sn2 * f1;
                mn = Mn;
            }
            if ((lane & 3) == 0)
                part[rloc][wn] = make_float4(md, sd, mn, sn);
        }
    }
    __syncthreads();

    // --- final per-row merge of the 4 warp partials; write global partials
    if (tid < 128) {
        float4 p = part[tid][0];
        float md = p.x, sd = p.y, mn = p.z, sn = p.w;
#pragma unroll
        for (int w = 1; w < 4; w++) {
            float4 q = part[tid][w];
            float M = fmaxf(md, q.x);
            sd = sd * __expf(md - M) + q.y * __expf(q.x - M);
            md = M;
            float Mn = fmaxf(mn, q.z);
            float f0 = (mn == -INFINITY) ? 0.f : __expf(mn - Mn);
            float f1 = (q.z == -INFINITY) ? 0.f : __expf(q.z - Mn);
            sn = sn * f0 + q.w * f1;
            mn = Mn;
        }
        size_t o = (size_t)blockIdx.x * B_ROWS + m0 + tid;
        g_pmd[o] = md;
        g_psd[o] = sd;
        g_pmn[o] = mn;
        g_psn[o] = sn;
    }
}

// ===========================================================================
// Kernel 3: combine 32 chunk-partials per row -> loss. Two independent
// LSE chains (halved dependent-latency), merged at the end.
// ===========================================================================
__global__ void combine_kernel(float* __restrict__ out) {
    int r = blockIdx.x * blockDim.x + threadIdx.x;
    if (r >= B_ROWS) return;
    float md[2] = {-INFINITY, -INFINITY}, sd[2] = {0.f, 0.f};
    float mn[2] = {-INFINITY, -INFINITY}, sn[2] = {0.f, 0.f};
#pragma unroll
    for (int h = 0; h < 2; h++) {
        for (int c = h * 16; c < h * 16 + 16; c++) {
            size_t o = (size_t)c * B_ROWS + r;
            float m2 = g_pmd[o], s2 = g_psd[o];
            float M = fmaxf(md[h], m2);
            sd[h] = sd[h] * __expf(md[h] - M) + s2 * __expf(m2 - M);
            md[h] = M;
            float mm = g_pmn[o], ss = g_psn[o];
            float Mn = fmaxf(mn[h], mm);
            float f0 = (mn[h] == -INFINITY) ? 0.f : __expf(mn[h] - Mn);
            float f1 = (mm == -INFINITY) ? 0.f : __expf(mm - Mn);
            sn[h] = sn[h] * f0 + ss * f1;
            mn[h] = Mn;
        }
    }
    float M = fmaxf(md[0], md[1]);
    float SD = sd[0] * __expf(md[0] - M) + sd[1] * __expf(md[1] - M);
    float Mn = fmaxf(mn[0], mn[1]);
    float f0 = (mn[0] == -INFINITY) ? 0.f : __expf(mn[0] - Mn);
    float f1 = (mn[1] == -INFINITY) ? 0.f : __expf(mn[1] - Mn);
    float SN = sn[0] * f0 + sn[1] * f1;
    out[r] = (M + logf(SD)) - (Mn + logf(SN));
}

// ===========================================================================
// Launch
// ===========================================================================
extern "C" void kernel_launch(void* const* d_in, const int* in_sizes, int n_in,
                              void* d_out, int out_size) {
    const float* feature = (const float*)d_in[0];
    const int* label = (const int*)d_in[1];
    const float* proto = (const float*)d_in[2];
    const int* plab = (const int*)d_in[3];
    float* out = (float*)d_out;

    int warps = B_ROWS + P_ROWS;
    prep_kernel<<<(warps * 32 + 255) / 256, 256>>>(feature, proto);

    dim3 grid(P_ROWS / BN, B_ROWS / BM);
    dce_mma_kernel<<<grid, 256>>>(label, plab);

    combine_kernel<<<(B_ROWS + 255) / 256, 256>>>(out);
}

// round 17
// speedup vs baseline: 1.5297x; 1.0166x over previous
#include <cuda_runtime.h>
#include <cuda_fp16.h>
#include <math.h>
#include <stdint.h>

// ===========================================================================
// Problem constants
// ===========================================================================
#define B_ROWS 8192
#define P_ROWS 4096
#define D_DIM  512
#define NCHUNK (P_ROWS / 128)     // 32 column chunks of 128 protos

#define BM 128
#define BN 128
#define NTK (D_DIM / 16)           // 32 k16 tiles
#define NTP (P_ROWS / 16)          // 256 n16 (tile-pair) blocks
#define NMT (B_ROWS / 16)          // 512 m16 tiles

// ===========================================================================
// Scratch (allocation-free)
// A in mma A-fragment order: [mt (512)][tk (32)][lane (32)] x uint4 (a0..a3)
// B in mma B-fragment order: [tk (32)][tp (256)][lane (32)] x uint4
//   uint4 = {tile 2tp: b0, b1, tile 2tp+1: b0, b1}
// ===========================================================================
__device__ uint4 g_Afrag[NMT * NTK * 32];
__device__ uint4 g_Bfrag[NTK * NTP * 32];
__device__ float g_fsq[B_ROWS];
__device__ float g_psq[P_ROWS];
__device__ float g_pmd[NCHUNK * B_ROWS];
__device__ float g_psd[NCHUNK * B_ROWS];
__device__ float g_pmn[NCHUNK * B_ROWS];
__device__ float g_psn[NCHUNK * B_ROWS];

#define MMA16816(c, a, b0, b1)                                                  \
    asm volatile("mma.sync.aligned.m16n8k16.row.col.f32.f16.f16.f32 "           \
        "{%0,%1,%2,%3}, {%4,%5,%6,%7}, {%8,%9}, {%0,%1,%2,%3};"                 \
        : "+f"((c)[0]), "+f"((c)[1]), "+f"((c)[2]), "+f"((c)[3])                \
        : "r"((a).x), "r"((a).y), "r"((a).z), "r"((a).w),                       \
          "r"(b0), "r"(b1))

// ===========================================================================
// Kernel 1 (R10 version — fastest measured): fp16 quantize + squared norms
// OF THE QUANTIZED vectors, writing both operands in mma fragment order.
// One warp per row, float2 loads.
// ===========================================================================
__global__ void prep_kernel(const float* __restrict__ feat,
                            const float* __restrict__ proto) {
    int warp = (blockIdx.x * blockDim.x + threadIdx.x) >> 5;
    int lane = threadIdx.x & 31;
    if (warp >= B_ROWS + P_ROWS) return;
    bool isA = warp < B_ROWS;
    int row = isA ? warp : warp - B_ROWS;
    const float* src = (isA ? feat : proto) + (size_t)row * D_DIM;

    float s = 0.f;
    if (isA) {
        uint32_t* dst = (uint32_t*)g_Afrag;
        int mt = row >> 4;
        int tr = row & 15;
        int rsel = (tr >> 3) & 1;            // a0/a1 select
        int lane_base = (tr & 7) * 4;
#pragma unroll
        for (int t = 0; t < 8; t++) {
            int k = t * 64 + lane * 2;
            float2 v = *(const float2*)(src + k);
            __half h0 = __float2half_rn(v.x);
            __half h1 = __float2half_rn(v.y);
            float q0 = __half2float(h0), q1 = __half2float(h1);
            s = fmaf(q0, q0, fmaf(q1, q1, s));
            uint32_t pack = (uint32_t)__half_as_ushort(h0)
                          | ((uint32_t)__half_as_ushort(h1) << 16);
            int tk = k >> 4;
            int kk = k & 15;
            int reg = rsel + ((kk >> 3) << 1);
            int lane_t = lane_base + ((kk & 7) >> 1);
            uint32_t idx = (uint32_t)(((mt * NTK + tk) * 32 + lane_t) * 4 + reg);
            dst[idx] = pack;
        }
    } else {
        uint32_t* dst = (uint32_t*)g_Bfrag;
        int pr = row & 7;            // n' within n8 tile
        int tp = row >> 4;           // tile-pair index
        int sub = (row >> 3) & 1;    // which tile of the pair
#pragma unroll
        for (int t = 0; t < 8; t++) {
            int k = t * 64 + lane * 2;
            float2 v = *(const float2*)(src + k);
            __half h0 = __float2half_rn(v.x);
            __half h1 = __float2half_rn(v.y);
            float q0 = __half2float(h0), q1 = __half2float(h1);
            s = fmaf(q0, q0, fmaf(q1, q1, s));
            uint32_t pack = (uint32_t)__half_as_ushort(h0)
                          | ((uint32_t)__half_as_ushort(h1) << 16);
            uint32_t idx = (uint32_t)((((k >> 4) * NTP + tp) * 32
                          + pr * 4 + ((k & 7) >> 1)) * 4
                          + sub * 2 + ((k >> 3) & 1));
            dst[idx] = pack;
        }
    }
#pragma unroll
    for (int m = 16; m; m >>= 1) s += __shfl_xor_sync(0xffffffffu, s, m);
    if (lane == 0) {
        if (isA) g_fsq[row] = s; else g_psq[row] = s;
    }
}

// ===========================================================================
// Kernel 2: pure LDG->mma.sync mainloop (64x32 warp tile — proven optimal
// for the 128-reg budget), in-register dual-LSE epilogue.
// B prefetch issued before A (B has lower cross-warp sharing -> likelier
// L1 miss; give it the longer head start).
// grid = (32 n-chunks, 64 m-tiles), 256 threads = 2(m) x 4(n) warps.
// ===========================================================================
__global__ __launch_bounds__(256, 2) void dce_mma_kernel(
    const int* __restrict__ label, const int* __restrict__ plab) {
    __shared__ float psq_s[128];
    __shared__ int plab_s[128];
    __shared__ float4 part[128][4];          // [row][wn] partials (8KB)

    const int tid = threadIdx.x;
    const int lane = tid & 31;
    const int wid = tid >> 5;
    const int wm = wid >> 2;       // 0..1
    const int wn = wid & 3;        // 0..3
    const int m0 = blockIdx.y * BM;
    const int n0 = blockIdx.x * BN;
    const int mt0 = (m0 >> 4) + wm * 4;    // first of this warp's 4 m16 tiles
    const int tp0 = (n0 >> 4) + wn * 2;    // first of this warp's 2 tile-pairs

    if (tid < 128) {
        psq_s[tid] = g_psq[n0 + tid];
        plab_s[tid] = plab[n0 + tid];
    }

    float acc[4][4][4];
#pragma unroll
    for (int i = 0; i < 4; i++)
#pragma unroll
        for (int j = 0; j < 4; j++)
#pragma unroll
            for (int q = 0; q < 4; q++) acc[i][j][q] = 0.f;

    const uint4* __restrict__ Af = g_Afrag;
    const uint4* __restrict__ Bf = g_Bfrag;

    uint4 a[2][4], b[2][2];
    // preload tk = 0 (B first)
    b[0][0] = Bf[((size_t)0 * NTP + tp0) * 32 + lane];
    b[0][1] = Bf[((size_t)0 * NTP + tp0 + 1) * 32 + lane];
#pragma unroll
    for (int mt = 0; mt < 4; mt++)
        a[0][mt] = Af[((size_t)(mt0 + mt) * NTK + 0) * 32 + lane];

#pragma unroll 2
    for (int tk = 0; tk < NTK; tk++) {
        int cur = tk & 1, nxt = cur ^ 1;
        if (tk + 1 < NTK) {
            b[nxt][0] = Bf[((size_t)(tk + 1) * NTP + tp0) * 32 + lane];
            b[nxt][1] = Bf[((size_t)(tk + 1) * NTP + tp0 + 1) * 32 + lane];
#pragma unroll
            for (int mt = 0; mt < 4; mt++)
                a[nxt][mt] = Af[((size_t)(mt0 + mt) * NTK + tk + 1) * 32 + lane];
        }
#pragma unroll
        for (int mt = 0; mt < 4; mt++) {
            MMA16816(acc[mt][0], a[cur][mt], b[cur][0].x, b[cur][0].y);
            MMA16816(acc[mt][1], a[cur][mt], b[cur][0].z, b[cur][0].w);
            MMA16816(acc[mt][2], a[cur][mt], b[cur][1].x, b[cur][1].y);
            MMA16816(acc[mt][3], a[cur][mt], b[cur][1].z, b[cur][1].w);
        }
    }

    __syncthreads();   // psq_s/plab_s visible

    // --- in-register epilogue: 8 row-instances per thread (4mt x 2 row-halves)
#pragma unroll
    for (int mt = 0; mt < 4; mt++) {
#pragma unroll
        for (int rh = 0; rh < 2; rh++) {
            int rloc = wm * 64 + mt * 16 + rh * 8 + (lane >> 2);
            int r = m0 + rloc;
            float fsq = g_fsq[r];
            int lab = label[r];
            float lg[8];
            float md = -INFINITY, mn = -INFINITY;
#pragma unroll
            for (int nt = 0; nt < 4; nt++) {
#pragma unroll
                for (int h = 0; h < 2; h++) {
                    int col = wn * 32 + nt * 8 + ((lane & 3) << 1) + h;
                    float dot = acc[mt][nt][rh * 2 + h];
                    float d2 = fmaxf(fsq + psq_s[col] - 2.0f * dot, 0.0f);
                    float l = -d2;
                    lg[nt * 2 + h] = l;
                    md = fmaxf(md, l);
                    if (plab_s[col] == lab) mn = fmaxf(mn, l);
                }
            }
            float sd = 0.f, sn = 0.f;
#pragma unroll
            for (int nt = 0; nt < 4; nt++) {
#pragma unroll
                for (int h = 0; h < 2; h++) {
                    int col = wn * 32 + nt * 8 + ((lane & 3) << 1) + h;
                    float l = lg[nt * 2 + h];
                    sd += __expf(l - md);
                    if (plab_s[col] == lab) sn += __expf(l - mn);
                }
            }
            // merge across the 4 quad lanes (same row, different cols)
#pragma unroll
            for (int ms = 1; ms <= 2; ms <<= 1) {
                float md2 = __shfl_xor_sync(0xffffffffu, md, ms);
                float sd2 = __shfl_xor_sync(0xffffffffu, sd, ms);
                float mn2 = __shfl_xor_sync(0xffffffffu, mn, ms);
                float sn2 = __shfl_xor_sync(0xffffffffu, sn, ms);
                float M = fmaxf(md, md2);
                sd = sd * __expf(md - M) + sd2 * __expf(md2 - M);
                md = M;
                float Mn = fmaxf(mn, mn2);
                float f0 = (mn == -INFINITY) ? 0.f : __expf(mn - Mn);
                float f1 = (mn2 == -INFINITY) ? 0.f : __expf(mn2 - Mn);
                sn = sn * f0 + sn2 * f1;
                mn = Mn;
            }
            if ((lane & 3) == 0)
                part[rloc][wn] = make_float4(md, sd, mn, sn);
        }
    }
    __syncthreads();

    // --- final per-row merge of the 4 warp partials; write global partials
    if (tid < 128) {
        float4 p = part[tid][0];
        float md = p.x, sd = p.y, mn = p.z, sn = p.w;
#pragma unroll
        for (int w = 1; w < 4; w++) {
            float4 q = part[tid][w];
            float M = fmaxf(md, q.x);
            sd = sd * __expf(md - M) + q.y * __expf(q.x - M);
            md = M;
            float Mn = fmaxf(mn, q.z);
            float f0 = (mn == -INFINITY) ? 0.f : __expf(mn - Mn);
            float f1 = (q.z == -INFINITY) ? 0.f : __expf(q.z - Mn);
            sn = sn * f0 + q.w * f1;
            mn = Mn;
        }
        size_t o = (size_t)blockIdx.x * B_ROWS + m0 + tid;
        g_pmd[o] = md;
        g_psd[o] = sd;
        g_pmn[o] = mn;
        g_psn[o] = sn;
    }
}

// ===========================================================================
// Kernel 3: combine 32 chunk-partials per row -> loss. FOUR independent
// LSE chains (8 partials each) to cut the dependent exp-chain latency.
// ===========================================================================
__global__ void combine_kernel(float* __restrict__ out) {
    int r = blockIdx.x * blockDim.x + threadIdx.x;
    if (r >= B_ROWS) return;
    float md[4], sd[4], mn[4], sn[4];
#pragma unroll
    for (int h = 0; h < 4; h++) {
        md[h] = -INFINITY; sd[h] = 0.f; mn[h] = -INFINITY; sn[h] = 0.f;
    }
#pragma unroll
    for (int h = 0; h < 4; h++) {
        for (int c = h * 8; c < h * 8 + 8; c++) {
            size_t o = (size_t)c * B_ROWS + r;
            float m2 = g_pmd[o], s2 = g_psd[o];
            float M = fmaxf(md[h], m2);
            sd[h] = sd[h] * __expf(md[h] - M) + s2 * __expf(m2 - M);
            md[h] = M;
            float mm = g_pmn[o], ss = g_psn[o];
            float Mn = fmaxf(mn[h], mm);
            float f0 = (mn[h] == -INFINITY) ? 0.f : __expf(mn[h] - Mn);
            float f1 = (mm == -INFINITY) ? 0.f : __expf(mm - Mn);
            sn[h] = sn[h] * f0 + ss * f1;
            mn[h] = Mn;
        }
    }
    // tree-merge the 4 chains
#pragma unroll
    for (int st = 0; st < 2; st++) {
        int n = 2 >> st;                      // pairs: (0,1),(2,3) then (0,2)
#pragma unroll
        for (int i = 0; i < n; i++) {
            int x = i * (2 << st), y = x + (1 << st);
            float M = fmaxf(md[x], md[y]);
            sd[x] = sd[x] * __expf(md[x] - M) + sd[y] * __expf(md[y] - M);
            md[x] = M;
            float Mn = fmaxf(mn[x], mn[y]);
            float f0 = (mn[x] == -INFINITY) ? 0.f : __expf(mn[x] - Mn);
            float f1 = (mn[y] == -INFINITY) ? 0.f : __expf(mn[y] - Mn);
            sn[x] = sn[x] * f0 + sn[y] * f1;
            mn[x] = Mn;
        }
    }
    out[r] = (md[0] + logf(sd[0])) - (mn[0] + logf(sn[0]));
}

// ===========================================================================
// Launch
// ===========================================================================
extern "C" void kernel_launch(void* const* d_in, const int* in_sizes, int n_in,
                              void* d_out, int out_size) {
    const float* feature = (const float*)d_in[0];
    const int* label = (const int*)d_in[1];
    const float* proto = (const float*)d_in[2];
    const int* plab = (const int*)d_in[3];
    float* out = (float*)d_out;

    int warps = B_ROWS + P_ROWS;
    prep_kernel<<<(warps * 32 + 255) / 256, 256>>>(feature, proto);

    dim3 grid(P_ROWS / BN, B_ROWS / BM);
    dce_mma_kernel<<<grid, 256>>>(label, plab);

    combine_kernel<<<(B_ROWS + 255) / 256, 256>>>(out);
}